// round 14
// baseline (speedup 1.0000x reference)
#include <cuda_runtime.h>
#include <math.h>

#define NB 32
#define NC 1024
#define NM 1024
#define ND 512
#define NR 64

#define CS_SPLIT 32             // c-chunks for p2a (32 c each)
#define KS_SPLIT 16             // d-chunks for p2b (32 d each)
#define D_CH (ND / KS_SPLIT)    // 32
#define ITILE 64                // i-tile for fused kernel
#define NG 16                   // c-groups in fused phase B

// ---- device scratch (static: no allocations allowed) ----
__device__ float g_tsum[NB * NC];
__device__ float g_rsum[NR];
__device__ float g_kpart[CS_SPLIT][NB * ND];
__device__ float g_vpart[CS_SPLIT][NB * ND];
__device__ float g_upart[KS_SPLIT][NB * NC];
__device__ float g_ypart[KS_SPLIT][NB * NC];
__device__ float g_u[NB * NC];
__device__ float g_y[NB * NC];

__device__ __forceinline__ float warp_sum(float v) {
    #pragma unroll
    for (int o = 16; o; o >>= 1) v += __shfl_down_sync(0xffffffffu, v, o);
    return v;
}

// ---------------------------------------------------------------------------
// k_tsum: blocks [0,4096): tsum[b,c] = sum_m T[b,c,m]  (warp/row, float4)
//         blocks [4096,4104): rsum[r] = sum_m R_full[r,m]
// ---------------------------------------------------------------------------
__global__ __launch_bounds__(256) void k_tsum(const float* __restrict__ T,
                                              const float* __restrict__ Rf) {
    if (blockIdx.x < 4096) {
        int row = blockIdx.x * 8 + (threadIdx.x >> 5);
        int lane = threadIdx.x & 31;
        const float4* T4 = reinterpret_cast<const float4*>(T) + (size_t)row * (NM / 4);
        float4 t[8];
        #pragma unroll
        for (int k = 0; k < 8; k++) t[k] = T4[k * 32 + lane];
        float acc = 0.f;
        #pragma unroll
        for (int k = 0; k < 8; k++)
            acc += (t[k].x + t[k].y) + (t[k].z + t[k].w);
        acc = warp_sum(acc);
        if (lane == 0) g_tsum[row] = acc;
    } else {
        int r = (blockIdx.x - 4096) * 8 + (threadIdx.x >> 5);   // 64 rows
        int lane = threadIdx.x & 31;
        const float4* R4 = reinterpret_cast<const float4*>(Rf) + (size_t)r * (NM / 4);
        float4 t[8];
        #pragma unroll
        for (int k = 0; k < 8; k++) t[k] = R4[k * 32 + lane];
        float acc = 0.f;
        #pragma unroll
        for (int k = 0; k < 8; k++)
            acc += (t[k].x + t[k].y) + (t[k].z + t[k].w);
        acc = warp_sum(acc);
        if (lane == 0) g_rsum[r] = acc;
    }
}

// ---------------------------------------------------------------------------
// k_p2a: kpart/vpart[cs][b,d] = sum_{c in chunk} tsum[b,c]*Wk/Wv[c,d]
// ---------------------------------------------------------------------------
__global__ __launch_bounds__(128) void k_p2a(const float* __restrict__ Wk,
                                             const float* __restrict__ Wv) {
    __shared__ float ts[NB][32];
    int d  = blockIdx.x * 128 + threadIdx.x;
    int c0 = blockIdx.y * 32;
    for (int e = threadIdx.x; e < NB * 32; e += 128)
        ts[e >> 5][e & 31] = g_tsum[(e >> 5) * NC + c0 + (e & 31)];
    __syncthreads();

    float aK[NB], aV[NB];
    #pragma unroll
    for (int b = 0; b < NB; b++) { aK[b] = 0.f; aV[b] = 0.f; }

    #pragma unroll 4
    for (int cc = 0; cc < 32; cc++) {
        int c = c0 + cc;
        float wk = Wk[(size_t)c * ND + d];
        float wv = Wv[(size_t)c * ND + d];
        #pragma unroll
        for (int b = 0; b < NB; b++) {
            float tv = ts[b][cc];
            aK[b] = fmaf(tv, wk, aK[b]);
            aV[b] = fmaf(tv, wv, aV[b]);
        }
    }
    #pragma unroll
    for (int b = 0; b < NB; b++) {
        g_kpart[blockIdx.y][b * ND + d] = aK[b];
        g_vpart[blockIdx.y][b * ND + d] = aV[b];
    }
}

// ---------------------------------------------------------------------------
// k_p2b: fuses kv-partial reduction + both GEMMs (no Wq transpose).
// ---------------------------------------------------------------------------
__global__ __launch_bounds__(128) void k_p2b(const float* __restrict__ Wq,
                                             const float* __restrict__ Wout) {
    __shared__ float ks[NB][D_CH], vs[NB][D_CH];
    int c  = blockIdx.x * 128 + threadIdx.x;
    int d0 = blockIdx.y * D_CH;

    for (int e = threadIdx.x; e < NB * D_CH; e += 128) {
        int addr = (e >> 5) * ND + d0 + (e & (D_CH - 1));
        float sk = 0.f, sv = 0.f;
        #pragma unroll
        for (int p = 0; p < CS_SPLIT; p++) {
            sk += g_kpart[p][addr];
            sv += g_vpart[p][addr];
        }
        ks[e >> 5][e & (D_CH - 1)] = sk;
        vs[e >> 5][e & (D_CH - 1)] = sv;
    }
    __syncthreads();

    float wqr[D_CH];
    {
        const float4* wq4 = reinterpret_cast<const float4*>(Wq + (size_t)c * ND + d0);
        #pragma unroll
        for (int q = 0; q < D_CH / 4; q++) {
            float4 v = wq4[q];
            wqr[q * 4 + 0] = v.x; wqr[q * 4 + 1] = v.y;
            wqr[q * 4 + 2] = v.z; wqr[q * 4 + 3] = v.w;
        }
    }

    float aU[NB], aY[NB];
    #pragma unroll
    for (int b = 0; b < NB; b++) { aU[b] = 0.f; aY[b] = 0.f; }

    #pragma unroll 4
    for (int dd = 0; dd < D_CH; dd++) {
        float wq = wqr[dd];
        float wo = Wout[(size_t)(d0 + dd) * NC + c];
        #pragma unroll
        for (int b = 0; b < NB; b++) {
            aU[b] = fmaf(ks[b][dd], wq, aU[b]);
            aY[b] = fmaf(vs[b][dd], wo, aY[b]);
        }
    }
    #pragma unroll
    for (int b = 0; b < NB; b++) {
        g_upart[blockIdx.y][b * NC + c] = aU[b];
        g_ypart[blockIdx.y][b * NC + c] = aY[b];
    }
}

// ---------------------------------------------------------------------------
// k_uy: finalize u/y once (float4), so fused blocks read only 8KB each.
// grid 32 x 256 (j indexes float4 < NB*NC/4 = 8192)
// ---------------------------------------------------------------------------
__global__ __launch_bounds__(256) void k_uy() {
    int j = blockIdx.x * 256 + threadIdx.x;
    float4 su = {0.f, 0.f, 0.f, 0.f}, sy = {0.f, 0.f, 0.f, 0.f};
    #pragma unroll
    for (int p = 0; p < KS_SPLIT; p++) {
        float4 a = reinterpret_cast<const float4*>(g_upart[p])[j];
        float4 c = reinterpret_cast<const float4*>(g_ypart[p])[j];
        su.x += a.x; su.y += a.y; su.z += a.z; su.w += a.w;
        sy.x += c.x; sy.y += c.y; sy.z += c.z; sy.w += c.w;
    }
    reinterpret_cast<float4*>(g_u)[j] = su;
    reinterpret_cast<float4*>(g_y)[j] = sy;
}

// ---------------------------------------------------------------------------
// k_fused: block = (64-wide i-tile, b); 256 threads; grid (16, 32) = 512.
//  A: us/y_s from g_u/g_y (L2-hot), rsum->rs
//  B: 16 c-groups x 16 lanes; s[i] = scale*sum_c us[c]*T[b,c,i];
//     deterministic 16-way smem reduce -> softmax -> w_s
//  C: out[b,c,i-tile] = w * y[c]  (streaming stores)
// ---------------------------------------------------------------------------
__global__ __launch_bounds__(256) void k_fused(const float* __restrict__ T,
                                               float* __restrict__ out) {
    __shared__ __align__(16) float us[NC];
    __shared__ __align__(16) float y_s[NC];
    __shared__ float rs[NR];
    __shared__ __align__(16) float w_s[ITILE];
    __shared__ __align__(16) float4 sred[NG][ITILE / 4];   // [c-group][i-lane] 4KB
    int b   = blockIdx.y;
    int i0  = blockIdx.x * ITILE;
    int tid = threadIdx.x;

    // phase A: one float4 per thread for each of u and y
    if (tid < NR) rs[tid] = g_rsum[tid];
    reinterpret_cast<float4*>(us)[tid]  = reinterpret_cast<const float4*>(g_u + b * NC)[tid];
    reinterpret_cast<float4*>(y_s)[tid] = reinterpret_cast<const float4*>(g_y + b * NC)[tid];
    __syncthreads();

    // phase B: group g handles c ≡ g (mod 16); lane owns float4 of i.
    {
        int g    = tid >> 4;           // 0..15
        int lane = tid & 15;           // 0..15
        const float* Tp = T + ((size_t)b * NC + g) * NM + i0 + 4 * lane;
        float4 acc = {0.f, 0.f, 0.f, 0.f};
        #pragma unroll 8
        for (int k = 0; k < NC / NG; k++) {
            float4 t = *reinterpret_cast<const float4*>(Tp + (size_t)k * NG * NM);
            float u = us[g + NG * k];
            acc.x = fmaf(u, t.x, acc.x);
            acc.y = fmaf(u, t.y, acc.y);
            acc.z = fmaf(u, t.z, acc.z);
            acc.w = fmaf(u, t.w, acc.w);
        }
        sred[g][lane] = acc;
    }
    __syncthreads();

    // reduce 16 groups (fixed order -> deterministic), softmax
    if (tid < ITILE) {
        const float* sf = reinterpret_cast<const float*>(sred);
        float s = 0.f;
        #pragma unroll
        for (int g = 0; g < NG; g++)
            s += sf[g * ITILE + tid];
        s *= 0.044194173824159216f;   // 1/sqrt(512)

        float mx = -1e30f;
        #pragma unroll
        for (int r = 0; r < NR; r++) mx = fmaxf(mx, s * rs[r]);
        float sp = 0.f, spr = 0.f;
        #pragma unroll
        for (int r = 0; r < NR; r++) {
            float p = __expf(fmaf(s, rs[r], -mx));
            sp += p;
            spr = fmaf(p, rs[r], spr);
        }
        w_s[tid] = spr / sp;
    }
    __syncthreads();

    // phase C: streaming broadcast write; 16 c's x 16 float4-lanes per pass
    int ci = tid >> 4;                 // 0..15
    int i4 = tid & 15;                 // float4 lane within i-tile
    float4 w4 = reinterpret_cast<const float4*>(w_s)[i4];
    float4* O4 = reinterpret_cast<float4*>(out);
    #pragma unroll 4
    for (int c = ci; c < NC; c += NG) {
        float yv = y_s[c];
        float4 o;
        o.x = w4.x * yv; o.y = w4.y * yv; o.z = w4.z * yv; o.w = w4.w * yv;
        __stcs(&O4[((size_t)(b * NC + c) * NM + i0) / 4 + i4], o);
    }
}

// ---------------------------------------------------------------------------
extern "C" void kernel_launch(void* const* d_in, const int* in_sizes, int n_in,
                              void* d_out, int out_size) {
    const float* T    = (const float*)d_in[0];
    const float* Wq   = (const float*)d_in[1];
    const float* Wk   = (const float*)d_in[2];
    const float* Wv   = (const float*)d_in[3];
    const float* Wout = (const float*)d_in[4];
    const float* Rf   = (const float*)d_in[5];
    float* out = (float*)d_out;

    k_tsum<<<4104, 256>>>(T, Rf);
    k_p2a<<<dim3(ND / 128, CS_SPLIT), 128>>>(Wk, Wv);
    k_p2b<<<dim3(NC / 128, KS_SPLIT), 128>>>(Wq, Wout);
    k_uy<<<32, 256>>>();
    k_fused<<<dim3(NM / ITILE, NB), 256>>>(T, out);
}

// round 16
// speedup vs baseline: 1.1246x; 1.1246x over previous
#include <cuda_runtime.h>
#include <math.h>

#define NB 32
#define NC 1024
#define NM 1024
#define ND 512
#define NR 64

#define CS_SPLIT 32             // c-chunks for p2a (32 c each)
#define KS_SPLIT 16             // d-chunks for p2b (32 d each)
#define D_CH (ND / KS_SPLIT)    // 32
#define ITILE 128               // i-tile for fused kernel
#define NG 16                   // c-groups in fused phase B (32 lanes each)

// ---- device scratch (static: no allocations allowed) ----
__device__ float g_tsum[NB * NC];
__device__ float g_rsum[NR];
__device__ float g_kpart[CS_SPLIT][NB * ND];
__device__ float g_vpart[CS_SPLIT][NB * ND];
__device__ float g_upart[KS_SPLIT][NB * NC];
__device__ float g_ypart[KS_SPLIT][NB * NC];

__device__ __forceinline__ float warp_sum(float v) {
    #pragma unroll
    for (int o = 16; o; o >>= 1) v += __shfl_down_sync(0xffffffffu, v, o);
    return v;
}

// ---------------------------------------------------------------------------
// k_tsum: blocks [0,4096): tsum[b,c] = sum_m T[b,c,m]  (warp/row, float4)
//         blocks [4096,4104): rsum[r] = sum_m R_full[r,m]
// ---------------------------------------------------------------------------
__global__ __launch_bounds__(256) void k_tsum(const float* __restrict__ T,
                                              const float* __restrict__ Rf) {
    if (blockIdx.x < 4096) {
        int row = blockIdx.x * 8 + (threadIdx.x >> 5);
        int lane = threadIdx.x & 31;
        const float4* T4 = reinterpret_cast<const float4*>(T) + (size_t)row * (NM / 4);
        float4 t[8];
        #pragma unroll
        for (int k = 0; k < 8; k++) t[k] = T4[k * 32 + lane];
        float acc = 0.f;
        #pragma unroll
        for (int k = 0; k < 8; k++)
            acc += (t[k].x + t[k].y) + (t[k].z + t[k].w);
        acc = warp_sum(acc);
        if (lane == 0) g_tsum[row] = acc;
    } else {
        int r = (blockIdx.x - 4096) * 8 + (threadIdx.x >> 5);   // 64 rows
        int lane = threadIdx.x & 31;
        const float4* R4 = reinterpret_cast<const float4*>(Rf) + (size_t)r * (NM / 4);
        float4 t[8];
        #pragma unroll
        for (int k = 0; k < 8; k++) t[k] = R4[k * 32 + lane];
        float acc = 0.f;
        #pragma unroll
        for (int k = 0; k < 8; k++)
            acc += (t[k].x + t[k].y) + (t[k].z + t[k].w);
        acc = warp_sum(acc);
        if (lane == 0) g_rsum[r] = acc;
    }
}

// ---------------------------------------------------------------------------
// k_p2a: kpart/vpart[cs][b,d] = sum_{c in chunk} tsum[b,c]*Wk/Wv[c,d]
// ---------------------------------------------------------------------------
__global__ __launch_bounds__(128) void k_p2a(const float* __restrict__ Wk,
                                             const float* __restrict__ Wv) {
    __shared__ float ts[NB][32];
    int d  = blockIdx.x * 128 + threadIdx.x;
    int c0 = blockIdx.y * 32;
    for (int e = threadIdx.x; e < NB * 32; e += 128)
        ts[e >> 5][e & 31] = g_tsum[(e >> 5) * NC + c0 + (e & 31)];
    __syncthreads();

    float aK[NB], aV[NB];
    #pragma unroll
    for (int b = 0; b < NB; b++) { aK[b] = 0.f; aV[b] = 0.f; }

    #pragma unroll 4
    for (int cc = 0; cc < 32; cc++) {
        int c = c0 + cc;
        float wk = Wk[(size_t)c * ND + d];
        float wv = Wv[(size_t)c * ND + d];
        #pragma unroll
        for (int b = 0; b < NB; b++) {
            float tv = ts[b][cc];
            aK[b] = fmaf(tv, wk, aK[b]);
            aV[b] = fmaf(tv, wv, aV[b]);
        }
    }
    #pragma unroll
    for (int b = 0; b < NB; b++) {
        g_kpart[blockIdx.y][b * ND + d] = aK[b];
        g_vpart[blockIdx.y][b * ND + d] = aV[b];
    }
}

// ---------------------------------------------------------------------------
// k_p2b: fuses kv-partial reduction + both GEMMs (no Wq transpose).
// ---------------------------------------------------------------------------
__global__ __launch_bounds__(128) void k_p2b(const float* __restrict__ Wq,
                                             const float* __restrict__ Wout) {
    __shared__ float ks[NB][D_CH], vs[NB][D_CH];
    int c  = blockIdx.x * 128 + threadIdx.x;
    int d0 = blockIdx.y * D_CH;

    for (int e = threadIdx.x; e < NB * D_CH; e += 128) {
        int addr = (e >> 5) * ND + d0 + (e & (D_CH - 1));
        float sk = 0.f, sv = 0.f;
        #pragma unroll
        for (int p = 0; p < CS_SPLIT; p++) {
            sk += g_kpart[p][addr];
            sv += g_vpart[p][addr];
        }
        ks[e >> 5][e & (D_CH - 1)] = sk;
        vs[e >> 5][e & (D_CH - 1)] = sv;
    }
    __syncthreads();

    float wqr[D_CH];
    {
        const float4* wq4 = reinterpret_cast<const float4*>(Wq + (size_t)c * ND + d0);
        #pragma unroll
        for (int q = 0; q < D_CH / 4; q++) {
            float4 v = wq4[q];
            wqr[q * 4 + 0] = v.x; wqr[q * 4 + 1] = v.y;
            wqr[q * 4 + 2] = v.z; wqr[q * 4 + 3] = v.w;
        }
    }

    float aU[NB], aY[NB];
    #pragma unroll
    for (int b = 0; b < NB; b++) { aU[b] = 0.f; aY[b] = 0.f; }

    #pragma unroll 4
    for (int dd = 0; dd < D_CH; dd++) {
        float wq = wqr[dd];
        float wo = Wout[(size_t)(d0 + dd) * NC + c];
        #pragma unroll
        for (int b = 0; b < NB; b++) {
            aU[b] = fmaf(ks[b][dd], wq, aU[b]);
            aY[b] = fmaf(vs[b][dd], wo, aY[b]);
        }
    }
    #pragma unroll
    for (int b = 0; b < NB; b++) {
        g_upart[blockIdx.y][b * NC + c] = aU[b];
        g_ypart[blockIdx.y][b * NC + c] = aY[b];
    }
}

// ---------------------------------------------------------------------------
// k_fused: block = (128-wide i-tile, b); 512 threads; grid (8, 32) = 256.
//  A: reduce upart->us[1024], ypart->y_s[1024], rsum->rs  (L2-hot partials)
//  B: 16 c-groups x 32 lanes; s[i] = scale*sum_c us[c]*T[b,c,i];
//     deterministic 16-way smem reduce -> softmax -> w_s
//  C: out[b,c,i-tile] = w * y[c]  (streaming stores, 512B/c segments)
// 512 threads + launch_bounds(512,2): ~27 resident warps/SM vs R13's ~14.
// ---------------------------------------------------------------------------
__global__ __launch_bounds__(512, 2) void k_fused(const float* __restrict__ T,
                                                  float* __restrict__ out) {
    __shared__ __align__(16) float us[NC];
    __shared__ __align__(16) float y_s[NC];
    __shared__ float rs[NR];
    __shared__ __align__(16) float w_s[ITILE];
    __shared__ __align__(16) float4 sred[NG][ITILE / 4];   // 8KB
    int b   = blockIdx.y;
    int i0  = blockIdx.x * ITILE;
    int tid = threadIdx.x;

    // phase A
    if (tid < NR) rs[tid] = g_rsum[tid];
    for (int e = tid; e < NC; e += 512) {
        float su = 0.f, sy = 0.f;
        #pragma unroll
        for (int p = 0; p < KS_SPLIT; p++) {
            su += g_upart[p][b * NC + e];
            sy += g_ypart[p][b * NC + e];
        }
        us[e] = su;
        y_s[e] = sy;
    }
    __syncthreads();

    // phase B: group g = tid>>5 handles c ≡ g (mod 16); lane owns float4 of i.
    {
        int g    = tid >> 5;           // 0..15
        int lane = tid & 31;           // 0..31
        const float* Tp = T + ((size_t)b * NC + g) * NM + i0 + 4 * lane;
        float4 acc = {0.f, 0.f, 0.f, 0.f};
        #pragma unroll 8
        for (int k = 0; k < NC / NG; k++) {
            float4 t = *reinterpret_cast<const float4*>(Tp + (size_t)k * NG * NM);
            float u = us[g + NG * k];
            acc.x = fmaf(u, t.x, acc.x);
            acc.y = fmaf(u, t.y, acc.y);
            acc.z = fmaf(u, t.z, acc.z);
            acc.w = fmaf(u, t.w, acc.w);
        }
        sred[g][lane] = acc;
    }
    __syncthreads();

    // reduce 16 groups (fixed order -> deterministic), softmax
    if (tid < ITILE) {
        const float* sf = reinterpret_cast<const float*>(sred);
        float s = 0.f;
        #pragma unroll
        for (int g = 0; g < NG; g++)
            s += sf[g * ITILE + tid];
        s *= 0.044194173824159216f;   // 1/sqrt(512)

        float mx = -1e30f;
        #pragma unroll
        for (int r = 0; r < NR; r++) mx = fmaxf(mx, s * rs[r]);
        float sp = 0.f, spr = 0.f;
        #pragma unroll
        for (int r = 0; r < NR; r++) {
            float p = __expf(fmaf(s, rs[r], -mx));
            sp += p;
            spr = fmaf(p, rs[r], spr);
        }
        w_s[tid] = spr / sp;
    }
    __syncthreads();

    // phase C: streaming broadcast write; 16 c's x 32 float4-lanes per pass
    int ci = tid >> 5;                 // 0..15
    int i4 = tid & 31;                 // float4 lane within i-tile
    float4 w4 = reinterpret_cast<const float4*>(w_s)[i4];
    float4* O4 = reinterpret_cast<float4*>(out);
    #pragma unroll 4
    for (int c = ci; c < NC; c += NG) {
        float yv = y_s[c];
        float4 o;
        o.x = w4.x * yv; o.y = w4.y * yv; o.z = w4.z * yv; o.w = w4.w * yv;
        __stcs(&O4[((size_t)(b * NC + c) * NM + i0) / 4 + i4], o);
    }
}

// ---------------------------------------------------------------------------
extern "C" void kernel_launch(void* const* d_in, const int* in_sizes, int n_in,
                              void* d_out, int out_size) {
    const float* T    = (const float*)d_in[0];
    const float* Wq   = (const float*)d_in[1];
    const float* Wk   = (const float*)d_in[2];
    const float* Wv   = (const float*)d_in[3];
    const float* Wout = (const float*)d_in[4];
    const float* Rf   = (const float*)d_in[5];
    float* out = (float*)d_out;

    k_tsum<<<4104, 256>>>(T, Rf);
    k_p2a<<<dim3(ND / 128, CS_SPLIT), 128>>>(Wk, Wv);
    k_p2b<<<dim3(NC / 128, KS_SPLIT), 128>>>(Wq, Wout);
    k_fused<<<dim3(NM / ITILE, NB), 512>>>(T, out);
}